// round 10
// baseline (speedup 1.0000x reference)
#include <cuda_runtime.h>
#include <math.h>
#include <stdint.h>

#define EB     128
#define PA     136    // A/H pitch ([k][perm(m)]); 136 % 32 == 8
#define LN_EPS 1e-5f

// ---- shared memory float offsets ----
#define O_BIAS 0        // 8 x 128
#define O_SS   1024     // [128][9]
#define O_SQ   2176     // [128][9]
#define O_MU   3328
#define O_RS   3456
#define O_EA   3584     // ea^T [64][136] -> ends 12288
#define O_A0   12288    // [32][136]
#define O_A1   16640    // -> ends 20992
#define O_B1   20992    // 3 stages x 8192 -> ends 45568
#define O_SH   12288    // overlay after GEMM1 (B1 stages dead by first write)
#define O_B2   29696    // 3 stages x 4096 -> ends 41984
#define O_TOT  45568    // 182272 bytes

// fragment-major weights:
// g_B1: chunk c(0..9): [ks 0..3][nb 0..31][lane 0..31][pair 0..1]
//   value = Bcol[k = c*32+ks*8+(lane&3)+4*pair][n = nb*8+(lane>>2)]
//   where Bcol col j: wn=j>>5, jj=j&31; jj<16 -> W1[:,16wn+jj] else Wg[:,16wn+jj-16]
__device__ __align__(16) float g_B1[320 * 256];
__device__ __align__(16) float g_W2[128 * 128];
__device__ __align__(16) float g_Wr[64 * 128];

__device__ __forceinline__ float tf32r(float x) {
    float r; asm("cvt.rna.tf32.f32 %0, %1;" : "=f"(r) : "f"(x)); return r;
}
__device__ __forceinline__ uint32_t smem_u32(const void* p) {
    uint32_t a;
    asm("{ .reg .u64 t; cvta.to.shared.u64 t, %1; cvt.u32.u64 %0, t; }" : "=r"(a) : "l"(p));
    return a;
}
__device__ __forceinline__ void cpa16(uint32_t sa, const void* g) {
    asm volatile("cp.async.cg.shared.global [%0], [%1], 16;" :: "r"(sa), "l"(g));
}
__device__ __forceinline__ void cpa_commit() {
    asm volatile("cp.async.commit_group;" ::: "memory");
}
template <int N>
__device__ __forceinline__ void cpa_wait() {
    asm volatile("cp.async.wait_group %0;" :: "n"(N) : "memory");
}
__device__ __forceinline__ void mma8(float* c, const float* a, const float* b) {
    asm volatile(
        "mma.sync.aligned.m16n8k8.row.col.f32.tf32.tf32.f32 "
        "{%0,%1,%2,%3}, {%4,%5,%6,%7}, {%8,%9}, {%0,%1,%2,%3};"
        : "+f"(c[0]), "+f"(c[1]), "+f"(c[2]), "+f"(c[3])
        : "r"(__float_as_uint(a[0])), "r"(__float_as_uint(a[1])),
          "r"(__float_as_uint(a[2])), "r"(__float_as_uint(a[3])),
          "r"(__float_as_uint(b[0])), "r"(__float_as_uint(b[1])));
}
__device__ __forceinline__ int permM(int m) {
    return ((m >> 4) << 4) | ((m & 7) << 1) | ((m >> 3) & 1);
}

// ---------------- prep: fragment-major tf32 weights ----------------
__global__ void prep_weights(const float* __restrict__ W1, const float* __restrict__ Wg,
                             const float* __restrict__ W2, const float* __restrict__ Wr) {
    const int b = blockIdx.x, t = threadIdx.x;
    if (b < 320) {
        const int o = b * 256 + t;
        const int pair = o & 1, lane = (o >> 1) & 31, nb = (o >> 6) & 31;
        const int ks = (o >> 11) & 3, c = o >> 13;
        const int k = c * 32 + ks * 8 + (lane & 3) + 4 * pair;
        const int j = nb * 8 + (lane >> 2);
        const int wn = j >> 5, jj = j & 31;
        const float v = (jj < 16) ? W1[k * 128 + 16 * wn + jj]
                                  : Wg[k * 128 + 16 * wn + jj - 16];
        g_B1[o] = tf32r(v);
    } else if (b < 384) {
        const int o = (b - 320) * 256 + t;
        const int pair = o & 1, lane = (o >> 1) & 31, nb = (o >> 6) & 15;
        const int ks = (o >> 10) & 3, c = o >> 12;
        const int k = c * 32 + ks * 8 + (lane & 3) + 4 * pair;
        const int n = nb * 8 + (lane >> 2);
        g_W2[o] = tf32r(W2[k * 128 + n]);
    } else if (b < 416) {
        const int o = (b - 384) * 256 + t;
        const int pair = o & 1, lane = (o >> 1) & 31, nb = (o >> 6) & 15;
        const int ks = (o >> 10) & 3, c = o >> 12;
        const int k = c * 32 + ks * 8 + (lane & 3) + 4 * pair;
        const int n = nb * 8 + (lane >> 2);
        g_Wr[o] = tf32r(Wr[k * 128 + n]);
    }
}

__global__ __launch_bounds__(512)
void edge_updater_mma(const float* __restrict__ x, const int* __restrict__ ei,
                      const float* __restrict__ ea,
                      const float* __restrict__ b1, const float* __restrict__ g1,
                      const float* __restrict__ be1, const float* __restrict__ b2,
                      const float* __restrict__ bg, const float* __restrict__ br,
                      const float* __restrict__ g2, const float* __restrict__ be2,
                      float* __restrict__ out, int E) {
    extern __shared__ float smem[];
    const uint32_t sbase = smem_u32(smem);
    const int tid  = threadIdx.x;
    const int lane = tid & 31;
    const int lr   = lane >> 2;
    const int lc   = lane & 3;
    const int wid  = tid >> 5;
    const int wy   = wid & 1;
    const int wn   = wid >> 1;
    const int e0   = blockIdx.x * EB;

    const int m_g  = tid & 127;
    const int kb_g = tid >> 7;
    const int pm_g = permM(m_g);
    int eg = e0 + m_g; if (eg >= E) eg = E - 1;
    const int idx_src = ei[eg];
    const int idx_dst = ei[E + eg];

    if (tid < 128) {
        smem[O_BIAS + 0   + tid] = b1[tid];
        smem[O_BIAS + 128 + tid] = g1[tid];
        smem[O_BIAS + 256 + tid] = be1[tid];
        smem[O_BIAS + 384 + tid] = bg[tid];
        smem[O_BIAS + 512 + tid] = b2[tid];
        smem[O_BIAS + 640 + tid] = br[tid];
        smem[O_BIAS + 768 + tid] = g2[tid];
        smem[O_BIAS + 896 + tid] = be2[tid];
    }

    auto loadB1 = [&](int c) {
        const uint32_t sb = sbase + (O_B1 + (c % 3) * 8192) * 4;
        const float* gsrc = g_B1 + (size_t)c * 8192;
#pragma unroll
        for (int i = 0; i < 4; i++) {
            int f = tid + i * 512;
            cpa16(sb + (uint32_t)f * 16, gsrc + f * 4);
        }
    };
    auto loadB2 = [&](int j) {
        const uint32_t sb = sbase + (O_B2 + (j % 3) * 4096) * 4;
        const float* gsrc = (j < 4) ? (g_W2 + (size_t)j * 4096)
                                    : (g_Wr + (size_t)(j - 4) * 4096);
#pragma unroll
        for (int i = 0; i < 2; i++) {
            int f = tid + i * 512;
            cpa16(sb + (uint32_t)f * 16, gsrc + f * 4);
        }
    };

    loadB1(0); cpa_commit();
    loadB1(1); cpa_commit();

    // ---- ea^T gather [64 k][perm m] ----
    {
        const float4* src = (const float4*)(ea + (size_t)eg * 64);
#pragma unroll
        for (int i = 0; i < 4; i++) {
            int k0 = kb_g * 16 + i * 4;
            float4 v = src[k0 >> 2];
            smem[O_EA + (k0 + 0) * PA + pm_g] = tf32r(v.x);
            smem[O_EA + (k0 + 1) * PA + pm_g] = tf32r(v.y);
            smem[O_EA + (k0 + 2) * PA + pm_g] = tf32r(v.z);
            smem[O_EA + (k0 + 3) * PA + pm_g] = tf32r(v.w);
        }
    }

    auto ldA = [&](int c, float4& r0, float4& r1) {
        const int idx = (c < 4) ? idx_src : idx_dst;
        const float* p = x + (size_t)idx * 128 + (c & 3) * 32 + kb_g * 8;
        r0 = *(const float4*)p;
        r1 = *(const float4*)(p + 4);
    };
    auto stA = [&](int c, const float4& r0, const float4& r1) {
        float* dst = smem + ((c & 1) ? O_A1 : O_A0);
        const int k0 = kb_g * 8;
        dst[(k0 + 0) * PA + pm_g] = tf32r(r0.x);
        dst[(k0 + 1) * PA + pm_g] = tf32r(r0.y);
        dst[(k0 + 2) * PA + pm_g] = tf32r(r0.z);
        dst[(k0 + 3) * PA + pm_g] = tf32r(r0.w);
        dst[(k0 + 4) * PA + pm_g] = tf32r(r1.x);
        dst[(k0 + 5) * PA + pm_g] = tf32r(r1.y);
        dst[(k0 + 6) * PA + pm_g] = tf32r(r1.z);
        dst[(k0 + 7) * PA + pm_g] = tf32r(r1.w);
    };

    {
        float4 a0, a1;
        ldA(0, a0, a1);
        stA(0, a0, a1);
    }

    // ---- GEMM1 ----
    float c1[4][4][4];
#pragma unroll
    for (int mi = 0; mi < 4; mi++)
#pragma unroll
        for (int ni = 0; ni < 4; ni++)
#pragma unroll
            for (int r = 0; r < 4; r++) c1[mi][ni][r] = 0.f;

    const int arow = lr * 2;

#pragma unroll 1
    for (int c = 0; c < 10; c++) {
        float4 a0, a1;
        if (c + 1 < 8) ldA(c + 1, a0, a1);
        if (c < 9) cpa_wait<1>(); else cpa_wait<0>();
        __syncthreads();
        if (c + 2 < 10) { loadB1(c + 2); cpa_commit(); }

        const float* Ab = (c < 8) ? (smem + ((c & 1) ? O_A1 : O_A0))
                                  : (smem + O_EA + (c - 8) * 32 * PA);
        const float* Bb = smem + O_B1 + (c % 3) * 8192;
#pragma unroll
        for (int kk = 0; kk < 4; kk++) {
            const float* Alo = Ab + (kk * 8 + lc) * PA + (wy * 4) * 16 + arow;
            const float* Ahi = Alo + 4 * PA;
            float af[4][4];
#pragma unroll
            for (int mi = 0; mi < 4; mi++) {
                float2 p0 = *(const float2*)(Alo + mi * 16);
                float2 p1 = *(const float2*)(Ahi + mi * 16);
                af[mi][0] = p0.x; af[mi][1] = p0.y;
                af[mi][2] = p1.x; af[mi][3] = p1.y;
            }
#pragma unroll
            for (int ni = 0; ni < 4; ni++) {
                float2 bp = *(const float2*)(Bb + (size_t)(kk * 32 + wn * 4 + ni) * 64 + lane * 2);
                float bf[2] = { bp.x, bp.y };
#pragma unroll
                for (int mi = 0; mi < 4; mi++) mma8(c1[mi][ni], af[mi], bf);
            }
        }
        if (c + 1 < 8) stA(c + 1, a0, a1);
    }

    loadB2(0); cpa_commit();
    loadB2(1); cpa_commit();

    // ---- epilogue 1: +b1, LN1 partials, GELU -> sH; gate -> regs ----
    float sl[4][2], ql[4][2];
#pragma unroll
    for (int mi = 0; mi < 4; mi++)
#pragma unroll
        for (int rh = 0; rh < 2; rh++) {
            float s = 0.f, q = 0.f;
#pragma unroll
            for (int ni = 0; ni < 2; ni++)
#pragma unroll
                for (int rl = 0; rl < 2; rl++) {
                    const int n = 16 * wn + ni * 8 + 2 * lc + rl;
                    float v = c1[mi][ni][2 * rh + rl] + smem[O_BIAS + n];
                    c1[mi][ni][2 * rh + rl] = v;
                    s += v; q += v * v;
                }
            s += __shfl_xor_sync(0xffffffffu, s, 1);
            q += __shfl_xor_sync(0xffffffffu, q, 1);
            s += __shfl_xor_sync(0xffffffffu, s, 2);
            q += __shfl_xor_sync(0xffffffffu, q, 2);
            sl[mi][rh] = s; ql[mi][rh] = q;
        }
    if (lc == 0) {
#pragma unroll
        for (int mi = 0; mi < 4; mi++)
#pragma unroll
            for (int rh = 0; rh < 2; rh++) {
                const int m = wy * 64 + mi * 16 + lr + 8 * rh;
                smem[O_SS + m * 9 + wn] = sl[mi][rh];
                smem[O_SQ + m * 9 + wn] = ql[mi][rh];
            }
    }
    __syncthreads();
    if (tid < 128) {
        float s = 0.f, q = 0.f;
#pragma unroll
        for (int i = 0; i < 8; i++) {
            s += smem[O_SS + tid * 9 + i];
            q += smem[O_SQ + tid * 9 + i];
        }
        const float mu = s * (1.f / 128.f);
        const float var = q * (1.f / 128.f) - mu * mu;
        smem[O_MU + tid] = mu;
        smem[O_RS + tid] = rsqrtf(var + LN_EPS);
    }
    __syncthreads();

    float gate[4][2][4];
#pragma unroll
    for (int mi = 0; mi < 4; mi++)
#pragma unroll
        for (int rh = 0; rh < 2; rh++) {
            const int m = wy * 64 + mi * 16 + lr + 8 * rh;
            const int pm = (wy * 4 + mi) * 16 + lr * 2 + rh;   // permM(m)
            const float mu = smem[O_MU + m];
            const float rs = smem[O_RS + m];
#pragma unroll
            for (int ni = 0; ni < 2; ni++)
#pragma unroll
                for (int rl = 0; rl < 2; rl++) {
                    const int n = 16 * wn + ni * 8 + 2 * lc + rl;
                    float hv = (c1[mi][ni][2 * rh + rl] - mu) * rs
                               * smem[O_BIAS + 128 + n] + smem[O_BIAS + 256 + n];
                    float ge = 0.5f * hv * (1.f + erff(hv * 0.70710678118654752f));
                    smem[O_SH + n * PA + pm] = tf32r(ge);
                    const float gp = c1[mi][2 + ni][2 * rh + rl] + smem[O_BIAS + 384 + n];
                    gate[mi][ni][2 * rh + rl] = 1.f / (1.f + __expf(-gp));
                }
        }

    // ---- GEMM2 ----
    float cU[4][2][4], cR[4][2][4];
#pragma unroll
    for (int mi = 0; mi < 4; mi++)
#pragma unroll
        for (int ni = 0; ni < 2; ni++)
#pragma unroll
            for (int r = 0; r < 4; r++) { cU[mi][ni][r] = 0.f; cR[mi][ni][r] = 0.f; }

#pragma unroll 1
    for (int j = 0; j < 6; j++) {
        if (j < 5) cpa_wait<1>(); else cpa_wait<0>();
        __syncthreads();
        if (j + 2 < 6) { loadB2(j + 2); cpa_commit(); }

        const float* Ab = (j < 4) ? (smem + O_SH + j * 32 * PA)
                                  : (smem + O_EA + (j - 4) * 32 * PA);
        const float* Bb = smem + O_B2 + (j % 3) * 4096;
        float (*acc)[2][4] = (j < 4) ? cU : cR;
#pragma unroll
        for (int kk = 0; kk < 4; kk++) {
            const float* Alo = Ab + (kk * 8 + lc) * PA + (wy * 4) * 16 + arow;
            const float* Ahi = Alo + 4 * PA;
            float af[4][4];
#pragma unroll
            for (int mi = 0; mi < 4; mi++) {
                float2 p0 = *(const float2*)(Alo + mi * 16);
                float2 p1 = *(const float2*)(Ahi + mi * 16);
                af[mi][0] = p0.x; af[mi][1] = p0.y;
                af[mi][2] = p1.x; af[mi][3] = p1.y;
            }
#pragma unroll
            for (int ni = 0; ni < 2; ni++) {
                float2 bp = *(const float2*)(Bb + (size_t)(kk * 16 + wn * 2 + ni) * 64 + lane * 2);
                float bf[2] = { bp.x, bp.y };
#pragma unroll
                for (int mi = 0; mi < 4; mi++) mma8(acc[mi][ni], af[mi], bf);
            }
        }
    }

    // ---- epilogue 2 ----
#pragma unroll
    for (int mi = 0; mi < 4; mi++)
#pragma unroll
        for (int rh = 0; rh < 2; rh++) {
            float s = 0.f, q = 0.f;
#pragma unroll
            for (int ni = 0; ni < 2; ni++)
#pragma unroll
                for (int rl = 0; rl < 2; rl++) {
                    const int n = 16 * wn + ni * 8 + 2 * lc + rl;
                    const int r = 2 * rh + rl;
                    float v = (cU[mi][ni][r] + smem[O_BIAS + 512 + n]) * gate[mi][ni][r]
                              + cR[mi][ni][r] + smem[O_BIAS + 640 + n];
                    cU[mi][ni][r] = v;
                    s += v; q += v * v;
                }
            s += __shfl_xor_sync(0xffffffffu, s, 1);
            q += __shfl_xor_sync(0xffffffffu, q, 1);
            s += __shfl_xor_sync(0xffffffffu, s, 2);
            q += __shfl_xor_sync(0xffffffffu, q, 2);
            sl[mi][rh] = s; ql[mi][rh] = q;
        }
    __syncthreads();
    if (lc == 0) {
#pragma unroll
        for (int mi = 0; mi < 4; mi++)
#pragma unroll
            for (int rh = 0; rh < 2; rh++) {
                const int m = wy * 64 + mi * 16 + lr + 8 * rh;
                smem[O_SS + m * 9 + wn] = sl[mi][rh];
                smem[O_SQ + m * 9 + wn] = ql[mi][rh];
            }
    }
    __syncthreads();
    if (tid < 128) {
        float s = 0.f, q = 0.f;
#pragma unroll
        for (int i = 0; i < 8; i++) {
            s += smem[O_SS + tid * 9 + i];
            q += smem[O_SQ + tid * 9 + i];
        }
        const float mu = s * (1.f / 128.f);
        const float var = q * (1.f / 128.f) - mu * mu;
        smem[O_MU + tid] = mu;
        smem[O_RS + tid] = rsqrtf(var + LN_EPS);
    }
    __syncthreads();

#pragma unroll
    for (int mi = 0; mi < 4; mi++)
#pragma unroll
        for (int rh = 0; rh < 2; rh++) {
            const int m = wy * 64 + mi * 16 + lr + 8 * rh;
            const int e = e0 + m;
            if (e < E) {
                const float mu = smem[O_MU + m];
                const float rs = smem[O_RS + m];
#pragma unroll
                for (int ni = 0; ni < 2; ni++) {
                    const int n0 = 16 * wn + ni * 8 + 2 * lc;
                    float2 o;
                    o.x = (cU[mi][ni][2 * rh + 0] - mu) * rs
                          * smem[O_BIAS + 768 + n0] + smem[O_BIAS + 896 + n0];
                    o.y = (cU[mi][ni][2 * rh + 1] - mu) * rs
                          * smem[O_BIAS + 768 + n0 + 1] + smem[O_BIAS + 896 + n0 + 1];
                    *(float2*)(out + (size_t)e * 128 + n0) = o;
                }
            }
        }
}

extern "C" void kernel_launch(void* const* d_in, const int* in_sizes, int n_in,
                              void* d_out, int out_size) {
    const float* x   = (const float*)d_in[0];
    const int*   ei  = (const int*)d_in[1];
    const float* ea  = (const float*)d_in[2];
    const float* W1  = (const float*)d_in[3];
    const float* b1  = (const float*)d_in[4];
    const float* g1  = (const float*)d_in[5];
    const float* be1 = (const float*)d_in[6];
    const float* W2  = (const float*)d_in[7];
    const float* b2  = (const float*)d_in[8];
    const float* Wg  = (const float*)d_in[9];
    const float* bg  = (const float*)d_in[10];
    const float* Wr  = (const float*)d_in[11];
    const float* br  = (const float*)d_in[12];
    const float* g2  = (const float*)d_in[13];
    const float* be2 = (const float*)d_in[14];

    const int E = in_sizes[1] / 2;

    prep_weights<<<416, 256>>>(W1, Wg, W2, Wr);

    const size_t smem = O_TOT * sizeof(float);
    cudaFuncSetAttribute(edge_updater_mma,
                         cudaFuncAttributeMaxDynamicSharedMemorySize, (int)smem);
    const int blocks = (E + EB - 1) / EB;
    edge_updater_mma<<<blocks, 512, smem>>>(x, ei, ea, b1, g1, be1, b2, bg, br, g2, be2,
                                            (float*)d_out, E);
}

// round 11
// speedup vs baseline: 1.1244x; 1.1244x over previous
#include <cuda_runtime.h>
#include <math.h>
#include <stdint.h>

#define EB     64
#define PA     72     // [k][perm(m)] pitch; 72 % 32 == 8
#define LN_EPS 1e-5f

// ---- shared float offsets (per CTA: 24064 floats = 96256 B; 2 CTAs/SM) ----
#define O_BIAS 0        // 8 x 128
#define O_SS   1024     // [64][5]
#define O_SQ   1344
#define O_MU   1664
#define O_RS   1728
#define O_EA   1792     // ea^T [64][72] -> 6400
#define O_A0   6400     // [16][72]
#define O_A1   7552     // -> 8704
#define O_B1   8704     // 3 stages x 4096 -> 20992
#define O_SH   8704     // overlay: h^T [128][72] -> 17920 (B1 dead when written)
#define O_B2   17920    // 3 stages x 2048 -> 24064
#define O_TOT  24064

// fragment-major k16 weights:
// g_B1 chunk c(0..19): [ks 0..1][nb 0..31][lane][pair]
//   k = c*16+ks*8+(lane&3)+4*pair ; j = nb*8+(lane>>2)
//   col j: wn=j>>6, jj=j&63; jj<32 -> W1[:,32wn+jj] else Wg[:,32wn+jj-32]
__device__ __align__(16) float g_B1[320 * 256];
__device__ __align__(16) float g_W2[128 * 128];   // 8 chunks x 2048
__device__ __align__(16) float g_Wr[64 * 128];    // 4 chunks x 2048

__device__ __forceinline__ float tf32r(float x) {
    float r; asm("cvt.rna.tf32.f32 %0, %1;" : "=f"(r) : "f"(x)); return r;
}
__device__ __forceinline__ uint32_t smem_u32(const void* p) {
    uint32_t a;
    asm("{ .reg .u64 t; cvta.to.shared.u64 t, %1; cvt.u32.u64 %0, t; }" : "=r"(a) : "l"(p));
    return a;
}
__device__ __forceinline__ void cpa16(uint32_t sa, const void* g) {
    asm volatile("cp.async.cg.shared.global [%0], [%1], 16;" :: "r"(sa), "l"(g));
}
__device__ __forceinline__ void cpa_commit() {
    asm volatile("cp.async.commit_group;" ::: "memory");
}
template <int N>
__device__ __forceinline__ void cpa_wait() {
    asm volatile("cp.async.wait_group %0;" :: "n"(N) : "memory");
}
__device__ __forceinline__ void mma8(float* c, const float* a, const float* b) {
    asm volatile(
        "mma.sync.aligned.m16n8k8.row.col.f32.tf32.tf32.f32 "
        "{%0,%1,%2,%3}, {%4,%5,%6,%7}, {%8,%9}, {%0,%1,%2,%3};"
        : "+f"(c[0]), "+f"(c[1]), "+f"(c[2]), "+f"(c[3])
        : "r"(__float_as_uint(a[0])), "r"(__float_as_uint(a[1])),
          "r"(__float_as_uint(a[2])), "r"(__float_as_uint(a[3])),
          "r"(__float_as_uint(b[0])), "r"(__float_as_uint(b[1])));
}
__device__ __forceinline__ int permM(int m) {
    return ((m >> 4) << 4) | ((m & 7) << 1) | ((m >> 3) & 1);
}

// ---------------- prep: fragment-major tf32 weights (k16 tiles) ----------------
__global__ void prep_weights(const float* __restrict__ W1, const float* __restrict__ Wg,
                             const float* __restrict__ W2, const float* __restrict__ Wr) {
    const int b = blockIdx.x, t = threadIdx.x;
    if (b < 320) {
        const int o = b * 256 + t;
        const int pair = o & 1, lane = (o >> 1) & 31, nb = (o >> 6) & 31;
        const int ks = (o >> 11) & 1, c = o >> 12;
        const int k = c * 16 + ks * 8 + (lane & 3) + 4 * pair;
        const int j = nb * 8 + (lane >> 2);
        const int wn = j >> 6, jj = j & 63;
        const float v = (jj < 32) ? W1[k * 128 + 32 * wn + jj]
                                  : Wg[k * 128 + 32 * wn + jj - 32];
        g_B1[o] = tf32r(v);
    } else if (b < 384) {
        const int o = (b - 320) * 256 + t;
        const int pair = o & 1, lane = (o >> 1) & 31, nb = (o >> 6) & 15;
        const int ks = (o >> 10) & 1, c = o >> 11;
        const int k = c * 16 + ks * 8 + (lane & 3) + 4 * pair;
        const int n = nb * 8 + (lane >> 2);
        g_W2[o] = tf32r(W2[k * 128 + n]);
    } else if (b < 416) {
        const int o = (b - 384) * 256 + t;
        const int pair = o & 1, lane = (o >> 1) & 31, nb = (o >> 6) & 15;
        const int ks = (o >> 10) & 1, c = o >> 11;
        const int k = c * 16 + ks * 8 + (lane & 3) + 4 * pair;
        const int n = nb * 8 + (lane >> 2);
        g_Wr[o] = tf32r(Wr[k * 128 + n]);
    }
}

__global__ __launch_bounds__(256, 2)
void edge_updater_mma(const float* __restrict__ x, const int* __restrict__ ei,
                      const float* __restrict__ ea,
                      const float* __restrict__ b1, const float* __restrict__ g1,
                      const float* __restrict__ be1, const float* __restrict__ b2,
                      const float* __restrict__ bg, const float* __restrict__ br,
                      const float* __restrict__ g2, const float* __restrict__ be2,
                      float* __restrict__ out, int E) {
    extern __shared__ float smem[];
    const uint32_t sbase = smem_u32(smem);
    const int tid  = threadIdx.x;
    const int lane = tid & 31;
    const int lr   = lane >> 2;
    const int lc   = lane & 3;
    const int wid  = tid >> 5;     // 0..7
    const int wy   = wid & 1;      // M half (32 rows)
    const int wn   = wid >> 1;     // 0..3 N group
    const int e0   = blockIdx.x * EB;

    const int m_g  = tid & 63;
    const int kb_g = tid >> 6;     // 0..3
    const int pm_g = permM(m_g);
    int eg = e0 + m_g; if (eg >= E) eg = E - 1;
    const int idx_src = ei[eg];
    const int idx_dst = ei[E + eg];

    if (tid < 128) {
        smem[O_BIAS + 0   + tid] = b1[tid];
        smem[O_BIAS + 128 + tid] = g1[tid];
        smem[O_BIAS + 256 + tid] = be1[tid];
        smem[O_BIAS + 384 + tid] = bg[tid];
        smem[O_BIAS + 512 + tid] = b2[tid];
        smem[O_BIAS + 640 + tid] = br[tid];
        smem[O_BIAS + 768 + tid] = g2[tid];
        smem[O_BIAS + 896 + tid] = be2[tid];
    }

    auto loadB1 = [&](int c) {   // 4096 floats
        const uint32_t sb = sbase + (O_B1 + (c % 3) * 4096) * 4;
        const float* gsrc = g_B1 + (size_t)c * 4096;
#pragma unroll
        for (int i = 0; i < 4; i++) {
            int f = tid + i * 256;
            cpa16(sb + (uint32_t)f * 16, gsrc + f * 4);
        }
    };
    auto loadB2 = [&](int j) {   // 2048 floats; j 0..7: W2, 8..11: Wr
        const uint32_t sb = sbase + (O_B2 + (j % 3) * 2048) * 4;
        const float* gsrc = (j < 8) ? (g_W2 + (size_t)j * 2048)
                                    : (g_Wr + (size_t)(j - 8) * 2048);
#pragma unroll
        for (int i = 0; i < 2; i++) {
            int f = tid + i * 256;
            cpa16(sb + (uint32_t)f * 16, gsrc + f * 4);
        }
    };

    loadB1(0); cpa_commit();
    loadB1(1); cpa_commit();

    // ---- ea^T gather [64 k][perm m] ----
    {
        const float4* src = (const float4*)(ea + (size_t)eg * 64);
#pragma unroll
        for (int i = 0; i < 4; i++) {
            int k0 = kb_g * 16 + i * 4;
            float4 v = src[k0 >> 2];
            smem[O_EA + (k0 + 0) * PA + pm_g] = tf32r(v.x);
            smem[O_EA + (k0 + 1) * PA + pm_g] = tf32r(v.y);
            smem[O_EA + (k0 + 2) * PA + pm_g] = tf32r(v.z);
            smem[O_EA + (k0 + 3) * PA + pm_g] = tf32r(v.w);
        }
    }

    // A gather: chunks 0..7 from x[src], 8..15 from x[dst]; each thread one float4
    auto ldA = [&](int c, float4& r0) {
        const int idx = (c < 8) ? idx_src : idx_dst;
        r0 = *(const float4*)(x + (size_t)idx * 128 + (c & 7) * 16 + kb_g * 4);
    };
    auto stA = [&](int c, const float4& r0) {
        float* dst = smem + ((c & 1) ? O_A1 : O_A0);
        const int k0 = kb_g * 4;
        dst[(k0 + 0) * PA + pm_g] = tf32r(r0.x);
        dst[(k0 + 1) * PA + pm_g] = tf32r(r0.y);
        dst[(k0 + 2) * PA + pm_g] = tf32r(r0.z);
        dst[(k0 + 3) * PA + pm_g] = tf32r(r0.w);
    };

    {
        float4 a0;
        ldA(0, a0);
        stA(0, a0);
    }

    // ---- GEMM1: C[64,256] = cat[64,320] @ B1, 20 k16 chunks ----
    float c1[2][8][4];
#pragma unroll
    for (int mi = 0; mi < 2; mi++)
#pragma unroll
        for (int ni = 0; ni < 8; ni++)
#pragma unroll
            for (int r = 0; r < 4; r++) c1[mi][ni][r] = 0.f;

#pragma unroll 1
    for (int c = 0; c < 20; c++) {
        float4 a0;
        if (c + 1 < 16) ldA(c + 1, a0);
        if (c < 19) cpa_wait<1>(); else cpa_wait<0>();
        __syncthreads();
        if (c + 2 < 20) { loadB1(c + 2); cpa_commit(); }

        const float* Ab = (c < 16) ? (smem + ((c & 1) ? O_A1 : O_A0))
                                   : (smem + O_EA + (c - 16) * 16 * PA);
        const float* Bb = smem + O_B1 + (c % 3) * 4096;
#pragma unroll
        for (int ks = 0; ks < 2; ks++) {
            const float* Alo = Ab + (ks * 8 + lc) * PA + wy * 32 + lr * 2;
            const float* Ahi = Alo + 4 * PA;
            float af[2][4];
#pragma unroll
            for (int mi = 0; mi < 2; mi++) {
                float2 p0 = *(const float2*)(Alo + mi * 16);
                float2 p1 = *(const float2*)(Ahi + mi * 16);
                af[mi][0] = p0.x; af[mi][1] = p0.y;
                af[mi][2] = p1.x; af[mi][3] = p1.y;
            }
#pragma unroll
            for (int ni = 0; ni < 8; ni++) {
                float2 bp = *(const float2*)(Bb + (size_t)(ks * 32 + wn * 8 + ni) * 64 + lane * 2);
                float bf[2] = { bp.x, bp.y };
#pragma unroll
                for (int mi = 0; mi < 2; mi++) mma8(c1[mi][ni], af[mi], bf);
            }
        }
        if (c + 1 < 16) stA(c + 1, a0);
    }

    // B2 stage 0 (A region dead) and stage 1 (B1 s2 tail, last read chunk 17)
    loadB2(0); cpa_commit();
    loadB2(1); cpa_commit();

    // ---- epilogue 1: +b1, LN1 partials, GELU -> sH; gate -> regs ----
    float sl[2][2], ql[2][2];
#pragma unroll
    for (int mi = 0; mi < 2; mi++)
#pragma unroll
        for (int rh = 0; rh < 2; rh++) {
            float s = 0.f, q = 0.f;
#pragma unroll
            for (int ni = 0; ni < 4; ni++)
#pragma unroll
                for (int rl = 0; rl < 2; rl++) {
                    const int n = 32 * wn + ni * 8 + 2 * lc + rl;
                    float v = c1[mi][ni][2 * rh + rl] + smem[O_BIAS + n];
                    c1[mi][ni][2 * rh + rl] = v;
                    s += v; q += v * v;
                }
            s += __shfl_xor_sync(0xffffffffu, s, 1);
            q += __shfl_xor_sync(0xffffffffu, q, 1);
            s += __shfl_xor_sync(0xffffffffu, s, 2);
            q += __shfl_xor_sync(0xffffffffu, q, 2);
            sl[mi][rh] = s; ql[mi][rh] = q;
        }
    if (lc == 0) {
#pragma unroll
        for (int mi = 0; mi < 2; mi++)
#pragma unroll
            for (int rh = 0; rh < 2; rh++) {
                const int m = wy * 32 + mi * 16 + lr + 8 * rh;
                smem[O_SS + m * 5 + wn] = sl[mi][rh];
                smem[O_SQ + m * 5 + wn] = ql[mi][rh];
            }
    }
    __syncthreads();
    if (tid < 64) {
        float s = 0.f, q = 0.f;
#pragma unroll
        for (int i = 0; i < 4; i++) {
            s += smem[O_SS + tid * 5 + i];
            q += smem[O_SQ + tid * 5 + i];
        }
        const float mu = s * (1.f / 128.f);
        const float var = q * (1.f / 128.f) - mu * mu;
        smem[O_MU + tid] = mu;
        smem[O_RS + tid] = rsqrtf(var + LN_EPS);
    }
    __syncthreads();

    float gate[2][4][4];
#pragma unroll
    for (int mi = 0; mi < 2; mi++)
#pragma unroll
        for (int rh = 0; rh < 2; rh++) {
            const int m = wy * 32 + mi * 16 + lr + 8 * rh;
            const int pm = (wy * 2 + mi) * 16 + lr * 2 + rh;   // permM(m)
            const float mu = smem[O_MU + m];
            const float rs = smem[O_RS + m];
#pragma unroll
            for (int ni = 0; ni < 4; ni++)
#pragma unroll
                for (int rl = 0; rl < 2; rl++) {
                    const int n = 32 * wn + ni * 8 + 2 * lc + rl;
                    float hv = (c1[mi][ni][2 * rh + rl] - mu) * rs
                               * smem[O_BIAS + 128 + n] + smem[O_BIAS + 256 + n];
                    float ge = 0.5f * hv * (1.f + erff(hv * 0.70710678118654752f));
                    smem[O_SH + n * PA + pm] = tf32r(ge);
                    const float gp = c1[mi][4 + ni][2 * rh + rl] + smem[O_BIAS + 384 + n];
                    gate[mi][ni][2 * rh + rl] = 1.f / (1.f + __expf(-gp));
                }
        }

    // ---- GEMM2: update = h @ W2 (j 0..7), res = ea @ Wr (j 8..11) ----
    float cU[2][4][4], cR[2][4][4];
#pragma unroll
    for (int mi = 0; mi < 2; mi++)
#pragma unroll
        for (int ni = 0; ni < 4; ni++)
#pragma unroll
            for (int r = 0; r < 4; r++) { cU[mi][ni][r] = 0.f; cR[mi][ni][r] = 0.f; }

#pragma unroll 1
    for (int j = 0; j < 12; j++) {
        if (j < 11) cpa_wait<1>(); else cpa_wait<0>();
        __syncthreads();
        if (j + 2 < 12) { loadB2(j + 2); cpa_commit(); }

        const float* Ab = (j < 8) ? (smem + O_SH + j * 16 * PA)
                                  : (smem + O_EA + (j - 8) * 16 * PA);
        const float* Bb = smem + O_B2 + (j % 3) * 2048;
        float (*acc)[4][4] = (j < 8) ? cU : cR;
#pragma unroll
        for (int ks = 0; ks < 2; ks++) {
            const float* Alo = Ab + (ks * 8 + lc) * PA + wy * 32 + lr * 2;
            const float* Ahi = Alo + 4 * PA;
            float af[2][4];
#pragma unroll
            for (int mi = 0; mi < 2; mi++) {
                float2 p0 = *(const float2*)(Alo + mi * 16);
                float2 p1 = *(const float2*)(Ahi + mi * 16);
                af[mi][0] = p0.x; af[mi][1] = p0.y;
                af[mi][2] = p1.x; af[mi][3] = p1.y;
            }
#pragma unroll
            for (int ni = 0; ni < 4; ni++) {
                float2 bp = *(const float2*)(Bb + (size_t)(ks * 16 + wn * 4 + ni) * 64 + lane * 2);
                float bf[2] = { bp.x, bp.y };
#pragma unroll
                for (int mi = 0; mi < 2; mi++) mma8(acc[mi][ni], af[mi], bf);
            }
        }
    }

    // ---- epilogue 2: v = (update+b2)*gate + res + br; LN2; store ----
#pragma unroll
    for (int mi = 0; mi < 2; mi++)
#pragma unroll
        for (int rh = 0; rh < 2; rh++) {
            float s = 0.f, q = 0.f;
#pragma unroll
            for (int ni = 0; ni < 4; ni++)
#pragma unroll
                for (int rl = 0; rl < 2; rl++) {
                    const int n = 32 * wn + ni * 8 + 2 * lc + rl;
                    const int r = 2 * rh + rl;
                    float v = (cU[mi][ni][r] + smem[O_BIAS + 512 + n]) * gate[mi][ni][r]
                              + cR[mi][ni][r] + smem[O_BIAS + 640 + n];
                    cU[mi][ni][r] = v;
                    s += v; q += v * v;
                }
            s += __shfl_xor_sync(0xffffffffu, s, 1);
            q += __shfl_xor_sync(0xffffffffu, q, 1);
            s += __shfl_xor_sync(0xffffffffu, s, 2);
            q += __shfl_xor_sync(0xffffffffu, q, 2);
            sl[mi][rh] = s; ql[mi][rh] = q;
        }
    __syncthreads();
    if (lc == 0) {
#pragma unroll
        for (int mi = 0; mi < 2; mi++)
#pragma unroll
            for (int rh = 0; rh < 2; rh++) {
                const int m = wy * 32 + mi * 16 + lr + 8 * rh;
                smem[O_SS + m * 5 + wn] = sl[mi][rh];
                smem[O_SQ + m * 5 + wn] = ql[mi][rh];
            }
    }
    __syncthreads();
    if (tid < 64) {
        float s = 0.f, q = 0.f;
#pragma unroll
        for (int i = 0; i < 4; i++) {
            s += smem[O_SS + tid * 5 + i];
            q += smem[O_SQ + tid * 5 + i];
        }
        const float mu = s * (1.f / 128.f);
        const float var = q * (1.f / 128.f) - mu * mu;
        smem[O_MU + tid] = mu;
        smem[O_RS + tid] = rsqrtf(var + LN_EPS);
    }
    __syncthreads();

#pragma unroll
    for (int mi = 0; mi < 2; mi++)
#pragma unroll
        for (int rh = 0; rh < 2; rh++) {
            const int m = wy * 32 + mi * 16 + lr + 8 * rh;
            const int e = e0 + m;
            if (e < E) {
                const float mu = smem[O_MU + m];
                const float rs = smem[O_RS + m];
#pragma unroll
                for (int ni = 0; ni < 4; ni++) {
                    const int n0 = 32 * wn + ni * 8 + 2 * lc;
                    float2 o;
                    o.x = (cU[mi][ni][2 * rh + 0] - mu) * rs
                          * smem[O_BIAS + 768 + n0] + smem[O_BIAS + 896 + n0];
                    o.y = (cU[mi][ni][2 * rh + 1] - mu) * rs
                          * smem[O_BIAS + 768 + n0 + 1] + smem[O_BIAS + 896 + n0 + 1];
                    *(float2*)(out + (size_t)e * 128 + n0) = o;
                }
            }
        }
}

extern "C" void kernel_launch(void* const* d_in, const int* in_sizes, int n_in,
                              void* d_out, int out_size) {
    const float* x   = (const float*)d_in[0];
    const int*   ei  = (const int*)d_in[1];
    const float* ea  = (const float*)d_in[2];
    const float* W1  = (const float*)d_in[3];
    const float* b1  = (const float*)d_in[4];
    const float* g1  = (const float*)d_in[5];
    const float* be1 = (const float*)d_in[6];
    const float* W2  = (const float*)d_in[7];
    const float* b2  = (const float*)d_in[8];
    const float* Wg  = (const float*)d_in[9];
    const float* bg  = (const float*)d_in[10];
    const float* Wr  = (const float*)d_in[11];
    const float* br  = (const float*)d_in[12];
    const float* g2  = (const float*)d_in[13];
    const float* be2 = (const float*)d_in[14];

    const int E = in_sizes[1] / 2;

    prep_weights<<<416, 256>>>(W1, Wg, W2, Wr);

    const size_t smem = O_TOT * sizeof(float);
    cudaFuncSetAttribute(edge_updater_mma,
                         cudaFuncAttributeMaxDynamicSharedMemorySize, (int)smem);
    const int blocks = (E + EB - 1) / EB;
    edge_updater_mma<<<blocks, 256, smem>>>(x, ei, ea, b1, g1, be1, b2, bg, br, g2, be2,
                                            (float*)d_out, E);
}

// round 15
// speedup vs baseline: 1.7660x; 1.5705x over previous
#include <cuda_runtime.h>
#include <cuda_fp16.h>
#include <math.h>
#include <stdint.h>

#define EB     64
#define LN_EPS 1e-5f

// ---- shared word(4B) offsets (per CTA: 18176 words = 72704 B; 2 CTAs/SM) ----
#define O_BIAS 0        // 8 x 128 floats
#define O_SS   1024     // [64][5]
#define O_SQ   1344
#define O_MU   1664
#define O_RS   1728
#define O_EA   1792     // ea halves: 4 subtiles [64m][16k] x 512 words -> 3840
#define O_A0   3840     // A chunk: 2 subtiles = 1024 words
#define O_A1   4864     // -> 5888
#define O_B1   5888     // 3 stages x 4096 words -> 18176
#define O_SH   5888     // overlay (= B1 stage 0): h 8 subtiles x 512 = 4096
#define O_B2   9984     // overlay (= B1 +4096): 3 stages x 2048 -> 16128
#define O_TOT  18176

// fragment-major packed-half weights (uint32 = half2 (k_even, k_odd)):
// g_B1h chunk c(0..9): [s16][nb 0..31][lane][word0..1]
//   word w: halves k = c*32 + s*16 + w*8 + 2*lc (+1), n-col j = nb*8 + lr
//   col j: wn=j>>6, jj=j&63; jj<32 -> W1[:,32wn+jj] else Wg[:,32wn+jj-32]
__device__ __align__(16) uint32_t g_B1h[40960];
__device__ __align__(16) uint32_t g_W2h[8192];   // 4 chunks x 2048
__device__ __align__(16) uint32_t g_Wrh[4096];   // 2 chunks x 2048

__device__ __forceinline__ uint32_t h2u(float a, float b) {
    __half2 h = __floats2half2_rn(a, b);
    return *reinterpret_cast<uint32_t*>(&h);
}
__device__ __forceinline__ uint32_t smem_u32(const void* p) {
    uint32_t a;
    asm("{ .reg .u64 t; cvta.to.shared.u64 t, %1; cvt.u32.u64 %0, t; }" : "=r"(a) : "l"(p));
    return a;
}
__device__ __forceinline__ void cpa16(uint32_t sa, const void* g) {
    asm volatile("cp.async.cg.shared.global [%0], [%1], 16;" :: "r"(sa), "l"(g));
}
__device__ __forceinline__ void cpa_commit() {
    asm volatile("cp.async.commit_group;" ::: "memory");
}
template <int N>
__device__ __forceinline__ void cpa_wait() {
    asm volatile("cp.async.wait_group %0;" :: "n"(N) : "memory");
}
__device__ __forceinline__ void mma16(float* c, const uint32_t* a, uint32_t b0, uint32_t b1) {
    asm volatile(
        "mma.sync.aligned.m16n8k16.row.col.f32.f16.f16.f32 "
        "{%0,%1,%2,%3}, {%4,%5,%6,%7}, {%8,%9}, {%0,%1,%2,%3};"
        : "+f"(c[0]), "+f"(c[1]), "+f"(c[2]), "+f"(c[3])
        : "r"(a[0]), "r"(a[1]), "r"(a[2]), "r"(a[3]), "r"(b0), "r"(b1));
}
// word swizzle within [m][16-half] subtile rows (8 words/row)
__device__ __forceinline__ int swz(int m) { return (m ^ (m >> 3)) & 7; }

// ---------------- prep: fragment-major packed-half weights ----------------
__global__ void prep_weights(const float* __restrict__ W1, const float* __restrict__ Wg,
                             const float* __restrict__ W2, const float* __restrict__ Wr) {
    const int b = blockIdx.x, t = threadIdx.x;
    if (b < 160) {                       // g_B1h: 40960 words
        const int o = b * 256 + t;
        const int word = o & 1, lane = (o >> 1) & 31, nb = (o >> 6) & 31;
        const int s = (o >> 11) & 1, c = o >> 12;
        const int lc = lane & 3, lr = lane >> 2;
        const int k = c * 32 + s * 16 + word * 8 + 2 * lc;
        const int j = nb * 8 + lr;
        const int wn = j >> 6, jj = j & 63;
        float lo, hi;
        if (jj < 32) { const int col = 32 * wn + jj;      lo = W1[k * 128 + col]; hi = W1[(k + 1) * 128 + col]; }
        else         { const int col = 32 * wn + jj - 32; lo = Wg[k * 128 + col]; hi = Wg[(k + 1) * 128 + col]; }
        g_B1h[o] = h2u(lo, hi);
    } else if (b < 192) {                // g_W2h: 8192 words
        const int o = (b - 160) * 256 + t;
        const int word = o & 1, lane = (o >> 1) & 31, nb = (o >> 6) & 15;
        const int s = (o >> 10) & 1, c = o >> 11;
        const int lc = lane & 3, lr = lane >> 2;
        const int k = c * 32 + s * 16 + word * 8 + 2 * lc;
        const int n = nb * 8 + lr;
        g_W2h[o] = h2u(W2[k * 128 + n], W2[(k + 1) * 128 + n]);
    } else if (b < 208) {                // g_Wrh: 4096 words
        const int o = (b - 192) * 256 + t;
        const int word = o & 1, lane = (o >> 1) & 31, nb = (o >> 6) & 15;
        const int s = (o >> 10) & 1, c = o >> 11;
        const int lc = lane & 3, lr = lane >> 2;
        const int k = c * 32 + s * 16 + word * 8 + 2 * lc;
        const int n = nb * 8 + lr;
        g_Wrh[o] = h2u(Wr[k * 128 + n], Wr[(k + 1) * 128 + n]);
    }
}

__global__ __launch_bounds__(256, 2)
void edge_updater_mma(const float* __restrict__ x, const int* __restrict__ ei,
                      const float* __restrict__ ea,
                      const float* __restrict__ b1, const float* __restrict__ g1,
                      const float* __restrict__ be1, const float* __restrict__ b2,
                      const float* __restrict__ bg, const float* __restrict__ br,
                      const float* __restrict__ g2, const float* __restrict__ be2,
                      float* __restrict__ out, int E) {
    extern __shared__ float smem[];
    uint32_t* usmem = (uint32_t*)smem;
    const uint32_t sbase = smem_u32(smem);
    const int tid  = threadIdx.x;
    const int lane = tid & 31;
    const int lr   = lane >> 2;
    const int lc   = lane & 3;
    const int wid  = tid >> 5;
    const int wy   = wid & 1;      // M half (32 rows)
    const int wn   = wid >> 1;     // 0..3 N group
    const int e0   = blockIdx.x * EB;

    // gather identity
    const int m_g = tid & 63;
    const int q_g = tid >> 6;      // 0..3
    const int s_g = q_g >> 1, p_g = q_g & 1;
    const int S_g = swz(m_g);
    int eg = e0 + m_g; if (eg >= E) eg = E - 1;
    const int idx_src = ei[eg];
    const int idx_dst = ei[E + eg];

    if (tid < 128) {
        smem[O_BIAS + 0   + tid] = b1[tid];
        smem[O_BIAS + 128 + tid] = g1[tid];
        smem[O_BIAS + 256 + tid] = be1[tid];
        smem[O_BIAS + 384 + tid] = bg[tid];
        smem[O_BIAS + 512 + tid] = b2[tid];
        smem[O_BIAS + 640 + tid] = br[tid];
        smem[O_BIAS + 768 + tid] = g2[tid];
        smem[O_BIAS + 896 + tid] = be2[tid];
    }

    auto loadB1 = [&](int c) {   // 4096 words = 1024 x 16B
        const uint32_t sb = sbase + (O_B1 + (c % 3) * 4096) * 4;
        const uint32_t* gsrc = g_B1h + (size_t)c * 4096;
#pragma unroll
        for (int i = 0; i < 4; i++) {
            int f = tid + i * 256;
            cpa16(sb + (uint32_t)f * 16, gsrc + f * 4);
        }
    };
    auto loadB2 = [&](int j) {   // 2048 words; j 0..3: W2, 4..5: Wr
        const uint32_t sb = sbase + (O_B2 + (j % 3) * 2048) * 4;
        const uint32_t* gsrc = (j < 4) ? (g_W2h + (size_t)j * 2048)
                                       : (g_Wrh + (size_t)(j - 4) * 2048);
#pragma unroll
        for (int i = 0; i < 2; i++) {
            int f = tid + i * 256;
            cpa16(sb + (uint32_t)f * 16, gsrc + f * 4);
        }
    };

    loadB1(0); cpa_commit();
    loadB1(1); cpa_commit();

    // ---- ea gather: 4 subtiles [64m][16k] half, swizzled ----
    {
        const float4* src = (const float4*)(ea + (size_t)eg * 64 + q_g * 16);
        float4 f[4];
#pragma unroll
        for (int i = 0; i < 4; i++) f[i] = src[i];
        uint32_t* dst = usmem + O_EA + q_g * 512 + m_g * 8;
#pragma unroll
        for (int w = 0; w < 8; w++) {
            const float* p = (const float*)&f[w >> 1] + (w & 1) * 2;
            dst[w ^ S_g] = h2u(p[0], p[1]);
        }
    }

    // A chunk gather: chunks 0..3 from x[src], 4..7 from x[dst]
    auto ldA = [&](int c, float4& f0, float4& f1) {
        const int idx = (c < 4) ? idx_src : idx_dst;
        const float* p = x + (size_t)idx * 128 + (c & 3) * 32 + s_g * 16 + p_g * 4;
        f0 = *(const float4*)p;
        f1 = *(const float4*)(p + 8);
    };
    auto stA = [&](int c, const float4& f0, const float4& f1) {
        uint32_t* dst = usmem + ((c & 1) ? O_A1 : O_A0) + s_g * 512 + m_g * 8;
        dst[(2 * p_g + 0) ^ S_g] = h2u(f0.x, f0.y);
        dst[(2 * p_g + 1) ^ S_g] = h2u(f0.z, f0.w);
        dst[(2 * p_g + 4) ^ S_g] = h2u(f1.x, f1.y);
        dst[(2 * p_g + 5) ^ S_g] = h2u(f1.z, f1.w);
    };

    {
        float4 f0, f1;
        ldA(0, f0, f1);
        stA(0, f0, f1);
    }

    // precomputed A-fragment word offsets: [mi][reg] (rows wy*32+mi*16 + lr/+8)
    uint32_t aoff[2][4];
#pragma unroll
    for (int mi = 0; mi < 2; mi++) {
        const int r0 = wy * 32 + mi * 16 + lr, r1 = r0 + 8;
        const int S0 = swz(r0), S1 = swz(r1);
        aoff[mi][0] = r0 * 8 + (lc ^ S0);
        aoff[mi][1] = r1 * 8 + (lc ^ S1);
        aoff[mi][2] = r0 * 8 + ((4 + lc) ^ S0);
        aoff[mi][3] = r1 * 8 + ((4 + lc) ^ S1);
    }

    // ---- GEMM1: C[64,256] = cat[64,320] @ B1, 10 k32 chunks ----
    float c1[2][8][4];
#pragma unroll
    for (int mi = 0; mi < 2; mi++)
#pragma unroll
        for (int ni = 0; ni < 8; ni++)
#pragma unroll
            for (int r = 0; r < 4; r++) c1[mi][ni][r] = 0.f;

#pragma unroll 1
    for (int c = 0; c < 10; c++) {
        float4 f0, f1;
        if (c + 1 < 8) ldA(c + 1, f0, f1);
        if (c < 9) cpa_wait<1>(); else cpa_wait<0>();
        __syncthreads();
        if (c + 2 < 10) { loadB1(c + 2); cpa_commit(); }

        const int Abase = (c < 8) ? ((c & 1) ? O_A1 : O_A0) : (O_EA + (c - 8) * 1024);
#pragma unroll
        for (int s = 0; s < 2; s++) {
            const uint32_t* As = usmem + Abase + s * 512;
            uint32_t af[2][4];
#pragma unroll
            for (int mi = 0; mi < 2; mi++) {
                af[mi][0] = As[aoff[mi][0]];
                af[mi][1] = As[aoff[mi][1]];
                af[mi][2] = As[aoff[mi][2]];
                af[mi][3] = As[aoff[mi][3]];
            }
            const uint32_t* Bs = usmem + O_B1 + (c % 3) * 4096 + (s * 32 + wn * 8) * 64 + lane * 2;
#pragma unroll
            for (int ni = 0; ni < 8; ni++) {
                uint2 b = *(const uint2*)(Bs + ni * 64);
                mma16(c1[0][ni], af[0], b.x, b.y);
                mma16(c1[1][ni], af[1], b.x, b.y);
            }
        }
        if (c + 1 < 8) stA(c + 1, f0, f1);
    }

    // prefetch GEMM2 B stages (targets O_B2 region, disjoint from sH)
    loadB2(0); cpa_commit();
    loadB2(1); cpa_commit();

    // ---- epilogue 1: +b1, LN1 partials, GELU -> sH (half); gate -> regs ----
    float sl[2][2], ql[2][2];
#pragma unroll
    for (int mi = 0; mi < 2; mi++)
#pragma unroll
        for (int rh = 0; rh < 2; rh++) {
            float s = 0.f, q = 0.f;
#pragma unroll
            for (int ni = 0; ni < 4; ni++)
#pragma unroll
                for (int rl = 0; rl < 2; rl++) {
                    const int n = 32 * wn + ni * 8 + 2 * lc + rl;
                    float v = c1[mi][ni][2 * rh + rl] + smem[O_BIAS + n];
                    c1[mi][ni][2 * rh + rl] = v;
                    s += v; q += v * v;
                }
            s += __shfl_xor_sync(0xffffffffu, s, 1);
            q += __shfl_xor_sync(0xffffffffu, q, 1);
            s += __shfl_xor_sync(0xffffffffu, s, 2);
            q += __shfl_xor_sync(0xffffffffu, q, 2);
            sl[mi][rh] = s; ql[mi][rh] = q;
        }
    if (lc == 0) {
#pragma unroll
        for (int mi = 0; mi < 2; mi++)
#pragma unroll
            for (int rh = 0; rh < 2; rh++) {
                const int m = wy * 32 + mi * 16 + lr + 8 * rh;
                smem[O_SS + m * 5 + wn] = sl[mi][rh];
                smem[O_SQ + m * 5 + wn] = ql[mi][rh];
            }
    }
    __syncthreads();
    if (tid < 64) {
        float s = 0.f, q = 0.f;
#pragma unroll
        for (int i = 0; i < 4; i++) {
            s += smem[O_SS + tid * 5 + i];
            q += smem[O_SQ + tid * 5 + i];
        }
        const float mu = s * (1.f / 128.f);
        const float var = q * (1.f / 128.f) - mu * mu;
        smem[O_MU + tid] = mu;
        smem[O_RS + tid] = rsqrtf(var + LN_EPS);
    }
    __syncthreads();

    float gate[2][4][4];
#pragma unroll
    for (int mi = 0; mi < 2; mi++)
#pragma unroll
        for (int rh = 0; rh < 2; rh++) {
            const int m = wy * 32 + mi * 16 + lr + 8 * rh;
            const int Sm = swz(m);
            const float mu = smem[O_MU + m];
            const float rs = smem[O_RS + m];
#pragma unroll
            for (int ni = 0; ni < 4; ni++) {
                float ge[2];
#pragma unroll
                for (int rl = 0; rl < 2; rl++) {
                    const int n = 32 * wn + ni * 8 + 2 * lc + rl;
                    float hv = (c1[mi][ni][2 * rh + rl] - mu) * rs
                               * smem[O_BIAS + 128 + n] + smem[O_BIAS + 256 + n];
                    ge[rl] = 0.5f * hv * (1.f + erff(hv * 0.70710678118654752f));
                    const float gp = c1[mi][4 + ni][2 * rh + rl] + smem[O_BIAS + 384 + n];
                    gate[mi][ni][2 * rh + rl] = 1.f / (1.f + __expf(-gp));
                }
                const int n0 = 32 * wn + ni * 8 + 2 * lc;
                const int sb = n0 >> 4;
                const int w = (n0 & 15) >> 1;
                usmem[O_SH + sb * 512 + m * 8 + (w ^ Sm)] = h2u(ge[0], ge[1]);
            }
        }

    // ---- GEMM2: update = h @ W2 (j 0..3), res = ea @ Wr (j 4..5), k32 chunks ----
    float cU[2][4][4], cR[2][4][4];
#pragma unroll
    for (int mi = 0; mi < 2; mi++)
#pragma unroll
        for (int ni = 0; ni < 4; ni++)
#pragma unroll
            for (int r = 0; r < 4; r++) { cU[mi][ni][r] = 0.f; cR[mi][ni][r] = 0.f; }

#pragma unroll 1
    for (int j = 0; j < 6; j++) {
        if (j < 5) cpa_wait<1>(); else cpa_wait<0>();
        __syncthreads();
        if (j + 2 < 6) { loadB2(j + 2); cpa_commit(); }

        const int Abase = (j < 4) ? (O_SH + 2 * j * 512) : (O_EA + 2 * (j - 4) * 512);
        float (*acc)[4][4] = (j < 4) ? cU : cR;
#pragma unroll
        for (int s = 0; s < 2; s++) {
            const uint32_t* As = usmem + Abase + s * 512;
            uint32_t af[2][4];
#pragma unroll
            for (int mi = 0; mi < 2; mi++) {
                af[mi][0] = As[aoff[mi][0]];
                af[mi][1] = As[aoff[mi][1]];
                af[mi][2] = As[aoff[mi][2]];
                af[mi][3] = As[aoff[mi][3]];
            }
            const uint32_t* Bs = usmem + O_B2 + (j % 3) * 2048 + (s * 16 + wn * 4) * 64 + lane * 2;
#pragma unroll
            for (int ni = 0; ni < 4; ni++) {
                uint2 b = *(const uint2*)(Bs + ni * 64);
                mma16(acc[0][ni], af[0], b.x, b.y);
                mma16(acc[1][ni], af[1], b.x, b.y);
            }
        }
    }

    // ---- epilogue 2: v = (update+b2)*gate + res + br; LN2; store ----
#pragma unroll
    for (int mi = 0; mi < 2; mi++)
#pragma unroll
        for (int rh = 0; rh < 2; rh++) {
            float s = 0.f, q = 0.f;
#pragma unroll
            for (int ni = 0; ni < 4; ni++)
#pragma unroll
                for (int rl = 0; rl < 2; rl++) {
                    const int n = 32 * wn + ni * 8 + 2 * lc + rl;
                    const int r = 2 * rh + rl;
                    float v = (cU[mi][ni][r] + smem[O_BIAS + 512 + n]) * gate[mi][ni][r]
                              + cR[mi][ni][r] + smem[O_BIAS + 640 + n];
                    cU[mi][ni][r] = v;
                    s += v; q += v * v;
                }
            s += __shfl_xor_sync(0xffffffffu, s, 1);
            q += __shfl_xor_sync(0xffffffffu, q, 1);
            s += __shfl_xor_sync(0xffffffffu, s, 2);
            q += __shfl_xor_sync(0xffffffffu, q, 2);
            sl[mi][rh] = s; ql[mi][rh] = q;
        }
    __syncthreads();
    if (lc == 0) {
#pragma unroll
        for (int mi = 0; mi < 2; mi++)
#pragma unroll
            for (int rh = 0; rh < 2; rh++) {
                const int m = wy * 32 + mi * 16 + lr + 8 * rh;
                smem[O_SS + m * 5 + wn] = sl[mi][rh];
                smem[O_SQ + m * 5 + wn] = ql[mi][rh];
            }
    }
    __syncthreads();
    if (tid < 64) {
        float s = 0.f, q = 0.f;
#pragma unroll
        for (int i = 0; i < 4; i++) {
            s += smem[O_SS + tid * 5 + i];
            q += smem[O_SQ + tid * 5 + i];
        }
        const float mu = s * (1.f / 128.f);
        const float var = q * (1.f / 128.f) - mu * mu;
        smem[O_MU + tid] = mu;
        smem[O_RS + tid] = rsqrtf(var + LN_EPS);
    }
    __syncthreads();

#pragma unroll
    for (int mi = 0; mi < 2; mi++)
#pragma unroll
        for (int rh = 0; rh < 2; rh++) {
            const int m = wy * 32 + mi * 16 + lr + 8 * rh;
            const int e = e0 + m;
            if (e < E) {
                const float mu = smem[O_MU + m];
                const float rs = smem[O_RS + m];
#pragma unroll
                for (int ni = 0; ni < 4; ni++) {
                    const int n0 = 32 * wn + ni * 8 + 2 * lc;
                    float2 o;
                    o.x = (cU[mi][ni][2 * rh + 0] - mu) * rs
                          * smem[O_BIAS + 768 + n0] + smem[O_BIAS + 896 + n0];
                    o.y = (cU[mi][ni][2 * rh + 1] - mu) * rs
                          * smem[O_BIAS + 768 + n0 + 1] + smem[O_BIAS + 896 + n0 + 1];
                    *(float2*)(out + (size_t)e * 128 + n0) = o;
                }
            }
        }
}

extern "C" void kernel_launch(void* const* d_in, const int* in_sizes, int n_in,
                              void* d_out, int out_size) {
    const float* x   = (const float*)d_in[0];
    const int*   ei  = (const int*)d_in[1];
    const float* ea  = (const float*)d_in[2];
    const float* W1  = (const float*)d_in[3];
    const float* b1  = (const float*)d_in[4];
    const float* g1  = (const float*)d_in[5];
    const float* be1 = (const float*)d_in[6];
    const float* W2  = (const float*)d_in[7];
    const float* b2  = (const float*)d_in[8];
    const float* Wg  = (const float*)d_in[9];
    const float* bg  = (const float*)d_in[10];
    const float* Wr  = (const float*)d_in[11];
    const float* br  = (const float*)d_in[12];
    const float* g2  = (const float*)d_in[13];
    const float* be2 = (const float*)d_in[14];

    const int E = in_sizes[1] / 2;

    prep_weights<<<208, 256>>>(W1, Wg, W2, Wr);

    const size_t smem = O_TOT * sizeof(float);
    cudaFuncSetAttribute(edge_updater_mma,
                         cudaFuncAttributeMaxDynamicSharedMemorySize, (int)smem);
    const int blocks = (E + EB - 1) / EB;
    edge_updater_mma<<<blocks, 256, smem>>>(x, ei, ea, b1, g1, be1, b2, bg, br, g2, be2,
                                            (float*)d_out, E);
}

// round 17
// speedup vs baseline: 2.4990x; 1.4151x over previous
#include <cuda_runtime.h>
#include <cuda_fp16.h>
#include <math.h>
#include <stdint.h>

#define EB     64
#define LN_EPS 1e-5f

// ---- shared word(4B) offsets (per CTA: 22272 words = 89088 B; 2 CTAs/SM) ----
#define O_BIAS 0        // 8 x 128 floats
#define O_SS   1024     // [64][5]
#define O_SQ   1344
#define O_MU   1664
#define O_RS   1728
#define O_EA   1792     // ea halves: 4 subtiles [64m][16k] x 512 words -> 3840
#define O_A0   3840     // A chunk: 2 subtiles = 1024 words
#define O_A1   4864     // -> 5888
#define O_B1   5888     // 3 stages x 4096 words -> 18176
#define O_SH   5888     // overlay (= B1 stage 0): h 8 subtiles x 512 = 4096
#define O_B2   9984     // overlay: 6 chunks x 2048 -> 22272
#define O_TOT  22272

// Subtile layout: [64 m][16 k] halves = [m][2 chunks of 16B], chunk swizzled:
//   word(m, ch, wic) = m*8 + ((ch ^ ((m>>2)&1))<<2) + wic
// B weights pair-packed fragment-major (uint4 = 2 n8-fragments):
// g_B1h chunk c(0..9): [(s*16+P)*128 + lane*4 + w], P=pair(0..15)
//   nb = 2P + (w>>1); b_half = w&1; k = c*32+s*16+b_half*8+2*(lane&3) (+1 hi)
//   col j = nb*8 + (lane>>2): wn=j>>6, jj=j&63; jj<32 -> W1[:,32wn+jj] else Wg
__device__ __align__(16) uint32_t g_B1h[40960];
__device__ __align__(16) uint32_t g_W2h[8192];   // 4 chunks x 2048, P 0..7
__device__ __align__(16) uint32_t g_Wrh[4096];   // 2 chunks x 2048

__device__ __forceinline__ uint32_t h2u(float a, float b) {
    __half2 h = __floats2half2_rn(a, b);
    return *reinterpret_cast<uint32_t*>(&h);
}
__device__ __forceinline__ uint32_t smem_u32(const void* p) {
    uint32_t a;
    asm("{ .reg .u64 t; cvta.to.shared.u64 t, %1; cvt.u32.u64 %0, t; }" : "=r"(a) : "l"(p));
    return a;
}
__device__ __forceinline__ void cpa16(uint32_t sa, const void* g) {
    asm volatile("cp.async.cg.shared.global [%0], [%1], 16;" :: "r"(sa), "l"(g));
}
__device__ __forceinline__ void cpa_commit() {
    asm volatile("cp.async.commit_group;" ::: "memory");
}
template <int N>
__device__ __forceinline__ void cpa_wait() {
    asm volatile("cp.async.wait_group %0;" :: "n"(N) : "memory");
}
__device__ __forceinline__ void mma16(float* c, const uint32_t* a, uint32_t b0, uint32_t b1) {
    asm volatile(
        "mma.sync.aligned.m16n8k16.row.col.f32.f16.f16.f32 "
        "{%0,%1,%2,%3}, {%4,%5,%6,%7}, {%8,%9}, {%0,%1,%2,%3};"
        : "+f"(c[0]), "+f"(c[1]), "+f"(c[2]), "+f"(c[3])
        : "r"(a[0]), "r"(a[1]), "r"(a[2]), "r"(a[3]), "r"(b0), "r"(b1));
}
__device__ __forceinline__ void ldsm4(uint32_t* r, uint32_t addr) {
    asm volatile("ldmatrix.sync.aligned.m8n8.x4.shared.b16 {%0,%1,%2,%3}, [%4];"
                 : "=r"(r[0]), "=r"(r[1]), "=r"(r[2]), "=r"(r[3]) : "r"(addr));
}

// ---------------- prep: pair-packed fragment-major half weights ----------------
__global__ void prep_weights(const float* __restrict__ W1, const float* __restrict__ Wg,
                             const float* __restrict__ W2, const float* __restrict__ Wr) {
    const int b = blockIdx.x, t = threadIdx.x;
    if (b < 160) {                       // g_B1h: 40960 words
        const int o = b * 256 + t;
        const int w = o & 3, lane = (o >> 2) & 31, P = (o >> 7) & 15;
        const int s = (o >> 11) & 1, c = o >> 12;
        const int lc = lane & 3, lr = lane >> 2;
        const int nb = 2 * P + (w >> 1);
        const int k = c * 32 + s * 16 + (w & 1) * 8 + 2 * lc;
        const int j = nb * 8 + lr;
        const int wn = j >> 6, jj = j & 63;
        float lo, hi;
        if (jj < 32) { const int col = 32 * wn + jj;      lo = W1[k * 128 + col]; hi = W1[(k + 1) * 128 + col]; }
        else         { const int col = 32 * wn + jj - 32; lo = Wg[k * 128 + col]; hi = Wg[(k + 1) * 128 + col]; }
        g_B1h[o] = h2u(lo, hi);
    } else if (b < 192) {                // g_W2h: 8192 words
        const int o = (b - 160) * 256 + t;
        const int w = o & 3, lane = (o >> 2) & 31, P = (o >> 7) & 7;
        const int s = (o >> 10) & 1, c = o >> 11;
        const int lc = lane & 3, lr = lane >> 2;
        const int nb = 2 * P + (w >> 1);
        const int k = c * 32 + s * 16 + (w & 1) * 8 + 2 * lc;
        const int n = nb * 8 + lr;
        g_W2h[o] = h2u(W2[k * 128 + n], W2[(k + 1) * 128 + n]);
    } else if (b < 208) {                // g_Wrh: 4096 words
        const int o = (b - 192) * 256 + t;
        const int w = o & 3, lane = (o >> 2) & 31, P = (o >> 7) & 7;
        const int s = (o >> 10) & 1, c = o >> 11;
        const int lc = lane & 3, lr = lane >> 2;
        const int nb = 2 * P + (w >> 1);
        const int k = c * 32 + s * 16 + (w & 1) * 8 + 2 * lc;
        const int n = nb * 8 + lr;
        g_Wrh[o] = h2u(Wr[k * 128 + n], Wr[(k + 1) * 128 + n]);
    }
}

__global__ __launch_bounds__(256, 2)
void edge_updater_mma(const float* __restrict__ x, const int* __restrict__ ei,
                      const float* __restrict__ ea,
                      const float* __restrict__ b1, const float* __restrict__ g1,
                      const float* __restrict__ be1, const float* __restrict__ b2,
                      const float* __restrict__ bg, const float* __restrict__ br,
                      const float* __restrict__ g2, const float* __restrict__ be2,
                      float* __restrict__ out, int E) {
    extern __shared__ float smem[];
    uint32_t* usmem = (uint32_t*)smem;
    const uint32_t sbase = smem_u32(smem);
    const int tid  = threadIdx.x;
    const int lane = tid & 31;
    const int lr   = lane >> 2;
    const int lc   = lane & 3;
    const int wid  = tid >> 5;
    const int wy   = wid & 1;      // M half (32 rows)
    const int wn   = wid >> 1;     // 0..3 N group
    const int e0   = blockIdx.x * EB;

    // gather identity: row m, (A: subtile s_t, half-chunk hc_t) / (ea: subtile q_g)
    const int m_t  = tid & 63;
    const int s_t  = (tid >> 6) & 1;
    const int hc_t = tid >> 7;
    const int q_g  = tid >> 6;
    int eg = e0 + m_t; if (eg >= E) eg = E - 1;
    const int idx_src = ei[eg];
    const int idx_dst = ei[E + eg];

    if (tid < 128) {
        smem[O_BIAS + 0   + tid] = b1[tid];
        smem[O_BIAS + 128 + tid] = g1[tid];
        smem[O_BIAS + 256 + tid] = be1[tid];
        smem[O_BIAS + 384 + tid] = bg[tid];
        smem[O_BIAS + 512 + tid] = b2[tid];
        smem[O_BIAS + 640 + tid] = br[tid];
        smem[O_BIAS + 768 + tid] = g2[tid];
        smem[O_BIAS + 896 + tid] = be2[tid];
    }

    auto loadB1 = [&](int c) {   // 4096 words = 1024 x 16B
        const uint32_t sb = sbase + (O_B1 + (c % 3) * 4096) * 4;
        const uint32_t* gsrc = g_B1h + (size_t)c * 4096;
#pragma unroll
        for (int i = 0; i < 4; i++) {
            int f = tid + i * 256;
            cpa16(sb + (uint32_t)f * 16, gsrc + f * 4);
        }
    };

    loadB1(0); cpa_commit();
    loadB1(1); cpa_commit();

    // ---- ea gather: 4 subtiles, chunk-swizzled, STS.128 ----
    {
        const float4* src = (const float4*)(ea + (size_t)eg * 64 + q_g * 16);
        float4 f0 = src[0], f1 = src[1], f2 = src[2], f3 = src[3];
        uint32_t* dst = usmem + O_EA + q_g * 512 + m_t * 8;
        const int b0 = ((m_t >> 2) & 1) << 2;
        uint4 v0 = { h2u(f0.x, f0.y), h2u(f0.z, f0.w), h2u(f1.x, f1.y), h2u(f1.z, f1.w) };
        uint4 v1 = { h2u(f2.x, f2.y), h2u(f2.z, f2.w), h2u(f3.x, f3.y), h2u(f3.z, f3.w) };
        *(uint4*)(dst + (0 ^ b0)) = v0;
        *(uint4*)(dst + (4 ^ b0)) = v1;
    }

    // A chunk gather: chunks 0..3 from x[src], 4..7 from x[dst]; 8 halves/thread
    auto ldA = [&](int c, float4& f0, float4& f1) {
        const int idx = (c < 4) ? idx_src : idx_dst;
        const float* p = x + (size_t)idx * 128 + (c & 3) * 32 + s_t * 16 + hc_t * 8;
        f0 = *(const float4*)p;
        f1 = *(const float4*)(p + 4);
    };
    auto stA = [&](int c, const float4& f0, const float4& f1) {
        uint32_t* dst = usmem + ((c & 1) ? O_A1 : O_A0) + s_t * 512 + m_t * 8;
        uint4 v = { h2u(f0.x, f0.y), h2u(f0.z, f0.w), h2u(f1.x, f1.y), h2u(f1.z, f1.w) };
        *(uint4*)(dst + ((hc_t << 2) ^ (((m_t >> 2) & 1) << 2))) = v;
    };

    {
        float4 f0, f1;
        ldA(0, f0, f1);
        stA(0, f0, f1);
    }

    // per-lane ldmatrix word offset (invariant over s, mi):
    // rows rbase(+16*mi), chunk = lane>>4, chunk-swizzle bit from rbase>>2
    const int rbase = wy * 32 + (lane & 7) + ((lane >> 3) & 1) * 8;
    const uint32_t woff = (uint32_t)(rbase * 8 + (((lane >> 4) ^ ((rbase >> 2) & 1)) << 2));

    // ---- GEMM1: C[64,256] = cat[64,320] @ B1, 10 k32 chunks ----
    float c1[2][8][4];
#pragma unroll
    for (int mi = 0; mi < 2; mi++)
#pragma unroll
        for (int ni = 0; ni < 8; ni++)
#pragma unroll
            for (int r = 0; r < 4; r++) c1[mi][ni][r] = 0.f;

#pragma unroll 1
    for (int c = 0; c < 10; c++) {
        float4 f0, f1;
        if (c + 1 < 8) ldA(c + 1, f0, f1);
        if (c < 9) cpa_wait<1>(); else cpa_wait<0>();
        __syncthreads();
        if (c + 2 < 10) { loadB1(c + 2); cpa_commit(); }

        const int Abase = (c < 8) ? ((c & 1) ? O_A1 : O_A0) : (O_EA + (c - 8) * 1024);
#pragma unroll
        for (int s = 0; s < 2; s++) {
            uint32_t af[2][4];
            const uint32_t abyte = sbase + (uint32_t)(Abase + s * 512) * 4 + woff * 4;
            ldsm4(af[0], abyte);
            ldsm4(af[1], abyte + 512);
            const uint32_t* Bs = usmem + O_B1 + (c % 3) * 4096 + (s * 16 + wn * 4) * 128 + lane * 4;
#pragma unroll
            for (int pi = 0; pi < 4; pi++) {
                uint4 b = *(const uint4*)(Bs + pi * 128);
                mma16(c1[0][2 * pi],     af[0], b.x, b.y);
                mma16(c1[1][2 * pi],     af[1], b.x, b.y);
                mma16(c1[0][2 * pi + 1], af[0], b.z, b.w);
                mma16(c1[1][2 * pi + 1], af[1], b.z, b.w);
            }
        }
        if (c + 1 < 8) stA(c + 1, f0, f1);
    }

    // preload ALL GEMM2 B chunks (24KB, one group) — overlaps epilogue 1
    {
#pragma unroll
        for (int j = 0; j < 6; j++) {
            const uint32_t sb = sbase + (O_B2 + j * 2048) * 4;
            const uint32_t* gsrc = (j < 4) ? (g_W2h + (size_t)j * 2048)
                                           : (g_Wrh + (size_t)(j - 4) * 2048);
#pragma unroll
            for (int i = 0; i < 2; i++) {
                int f = tid + i * 256;
                cpa16(sb + (uint32_t)f * 16, gsrc + f * 4);
            }
        }
        cpa_commit();
    }

    // ---- epilogue 1: +b1, LN1 partials, GELU -> sH (half); gate -> regs ----
    float sl[2][2], ql[2][2];
#pragma unroll
    for (int mi = 0; mi < 2; mi++)
#pragma unroll
        for (int rh = 0; rh < 2; rh++) {
            float s = 0.f, q = 0.f;
#pragma unroll
            for (int ni = 0; ni < 4; ni++)
#pragma unroll
                for (int rl = 0; rl < 2; rl++) {
                    const int n = 32 * wn + ni * 8 + 2 * lc + rl;
                    float v = c1[mi][ni][2 * rh + rl] + smem[O_BIAS + n];
                    c1[mi][ni][2 * rh + rl] = v;
                    s += v; q += v * v;
                }
            s += __shfl_xor_sync(0xffffffffu, s, 1);
            q += __shfl_xor_sync(0xffffffffu, q, 1);
            s += __shfl_xor_sync(0xffffffffu, s, 2);
            q += __shfl_xor_sync(0xffffffffu, q, 2);
            sl[mi][rh] = s; ql[mi][rh] = q;
        }
    if (lc == 0) {
#pragma unroll
        for (int mi = 0; mi < 2; mi++)
#pragma unroll
            for (int rh = 0; rh < 2; rh++) {
                const int m = wy * 32 + mi * 16 + lr + 8 * rh;
                smem[O_SS + m * 5 + wn] = sl[mi][rh];
                smem[O_SQ + m * 5 + wn] = ql[mi][rh];
            }
    }
    __syncthreads();
    if (tid < 64) {
        float s = 0.f, q = 0.f;
#pragma unroll
        for (int i = 0; i < 4; i++) {
            s += smem[O_SS + tid * 5 + i];
            q += smem[O_SQ + tid * 5 + i];
        }
        const float mu = s * (1.f / 128.f);
        const float var = q * (1.f / 128.f) - mu * mu;
        smem[O_MU + tid] = mu;
        smem[O_RS + tid] = rsqrtf(var + LN_EPS);
    }
    __syncthreads();

    float gate[2][4][4];
#pragma unroll
    for (int mi = 0; mi < 2; mi++)
#pragma unroll
        for (int rh = 0; rh < 2; rh++) {
            const int m = wy * 32 + mi * 16 + lr + 8 * rh;
            const int msw = ((m >> 2) & 1) << 2;
            const float mu = smem[O_MU + m];
            const float rs = smem[O_RS + m];
#pragma unroll
            for (int ni = 0; ni < 4; ni++) {
                float ge[2];
#pragma unroll
                for (int rl = 0; rl < 2; rl++) {
                    const int n = 32 * wn + ni * 8 + 2 * lc + rl;
                    float hv = (c1[mi][ni][2 * rh + rl] - mu) * rs
                               * smem[O_BIAS + 128 + n] + smem[O_BIAS + 256 + n];
                    ge[rl] = 0.5f * hv * (1.f + erff(hv * 0.70710678118654752f));
                    const float gp = c1[mi][4 + ni][2 * rh + rl] + smem[O_BIAS + 384 + n];
                    gate[mi][ni][2 * rh + rl] = 1.f / (1.f + __expf(-gp));
                }
                const int n0 = 32 * wn + ni * 8 + 2 * lc;
                const int sb2 = n0 >> 4;
                const int ch = ((n0 >> 3) & 1) << 2;
                usmem[O_SH + sb2 * 512 + m * 8 + (ch ^ msw) + lc] = h2u(ge[0], ge[1]);
            }
        }

    // ---- GEMM2: barrier-free burst (all B resident) ----
    float cU[2][4][4], cR[2][4][4];
#pragma unroll
    for (int mi = 0; mi < 2; mi++)
#pragma unroll
        for (int ni = 0; ni < 4; ni++)
#pragma unroll
            for (int r = 0; r < 4; r++) { cU[mi][ni][r] = 0.f; cR[mi][ni][r] = 0.f; }

    cpa_wait<0>();
    __syncthreads();   // B2 data + sH visible to all

#pragma unroll 1
    for (int j = 0; j < 6; j++) {
        const int Abase = (j < 4) ? (O_SH + 2 * j * 512) : (O_EA + 2 * (j - 4) * 512);
        float (*acc)[4][4] = (j < 4) ? cU : cR;
#pragma unroll
        for (int s = 0; s < 2; s++) {
            uint32_t af[2][4];
            const uint32_t abyte = sbase + (uint32_t)(Abase + s * 512) * 4 + woff * 4;
            ldsm4(af[0], abyte);
            ldsm4(af[1], abyte + 512);
            const uint32_t* Bs = usmem + O_B2 + j * 2048 + (s * 8 + wn * 2) * 128 + lane * 4;
#pragma unroll
            for (int pi = 0; pi < 2; pi++) {
                uint4 b = *(const uint4*)(Bs + pi * 128);
                mma16(acc[0][2 * pi],     af[0], b.x, b.y);
                mma16(acc[1][2 * pi],     af[1], b.x, b.y);
                mma16(acc[0][2 * pi + 1], af[0], b.z, b.w);
                mma16(acc[1][2 * pi + 1], af[1], b.z, b.w);
            }
        }
    }

    // ---- epilogue 2: v = (update+b2)*gate + res + br; LN2; store ----
#pragma unroll
    for (int mi = 0; mi < 2; mi++)
#pragma unroll
        for (int rh = 0; rh < 2; rh++) {
            float s = 0.f, q = 0.f;
#pragma unroll
            for (int ni = 0; ni < 4; ni++)
#pragma unroll
                for (int rl = 0; rl < 2; rl++) {
                    const int n = 32 * wn + ni * 8 + 2 * lc + rl;
                    const int r = 2 * rh + rl;
                    float v = (cU[mi][ni][r] + smem[O_BIAS + 512 + n]) * gate[mi][ni][r]
                              + cR[mi][ni][r] + smem[O_BIAS + 640 + n];
                    cU[mi][ni][r] = v;
                    s += v; q += v * v;
                }
            s += __shfl_xor_sync(0xffffffffu, s, 1);
            q += __shfl_xor_sync(0xffffffffu, q, 1);
            s += __shfl_xor_sync(0xffffffffu, s, 2);
            q += __shfl_xor_sync(0xffffffffu, q, 2);
            sl[mi][rh] = s; ql[mi][rh] = q;
        }
    __syncthreads();
    if (lc == 0) {
#pragma unroll
        for (int mi = 0; mi < 2; mi++)
#pragma unroll
            for (int rh = 0; rh < 2; rh++) {
                const int m = wy * 32 + mi * 16 + lr + 8 * rh;
                smem[O_SS + m * 5 + wn] = sl[mi][rh];
                smem[O_SQ + m * 5 + wn] = ql[mi][rh];
            }
    }
    __syncthreads();
    if (tid < 64) {
        float s = 0.f, q = 0.f;
#pragma unroll
        for (int i = 0; i < 4; i++) {
            s += smem[O_SS + tid * 5 + i];
            q += smem[O_SQ + tid * 5 + i];
        }
        const float mu = s * (1.f / 128.f);
        const float var = q * (1.f / 128.f) - mu * mu;
        smem[O_MU + tid] = mu;
        smem[O_RS + tid] = rsqrtf(var + LN_EPS);
    }
    __syncthreads();

#pragma unroll
    for (int mi = 0; mi < 2; mi++)
#pragma unroll
        for (int rh = 0; rh < 2; rh++) {
            const int m = wy * 32 + mi * 16 + lr + 8 * rh;
            const int e = e0 + m;
            if (e < E) {
                const float mu = smem[O_MU + m];
                const float rs = smem[O_RS + m];
#pragma unroll
                for (int ni = 0; ni < 4; ni++) {
                    const int n0 = 32 * wn + ni * 8 + 2 * lc;
                    float2 o;
                    o.x = (cU[mi][ni][2 * rh + 0] - mu) * rs
                          * smem[O_BIAS + 768 + n0] + smem[O_BIAS + 896 + n0];
                    o.y = (cU[mi][ni][2 * rh + 1] - mu) * rs
                          * smem[O_BIAS + 768 + n0 + 1] + smem[O_BIAS + 896 + n0 + 1];
                    *(float2*)(out + (size_t)e * 128 + n0) = o;
                }
            }
        }
}

extern "C" void kernel_launch(void* const* d_in, const int* in_sizes, int n_in,
                              void* d_out, int out_size) {
    const float* x   = (const float*)d_in[0];
    const int*   ei  = (const int*)d_in[1];
    const float* ea  = (const float*)d_in[2];
    const float* W1  = (const float*)d_in[3];
    const float* b1  = (const float*)d_in[4];
    const float* g1  = (const float*)d_in[5];
    const float* be1 = (const float*)d_in[6];
    const float* W2  = (const float*)d_in[7];
    const float* b2  = (const float*)d_in[8];
    const float* Wg  = (const float*)d_in[9];
    const float* bg  = (const float*)d_in[10];
    const float* Wr  = (const float*)d_in[11];
    const float* br  = (const float*)d_in[12];
    const float* g2  = (const float*)d_in[13];
    const float* be2 = (const float*)d_in[14];

    const int E = in_sizes[1] / 2;

    prep_weights<<<208, 256>>>(W1, Wg, W2, Wr);

    const size_t smem = O_TOT * sizeof(float);
    cudaFuncSetAttribute(edge_updater_mma,
                         cudaFuncAttributeMaxDynamicSharedMemorySize, (int)smem);
    const int blocks = (E + EB - 1) / EB;
    edge_updater_mma<<<blocks, 256, smem>>>(x, ei, ea, b1, g1, be1, b2, bg, br, g2, be2,
                                            (float*)d_out, E);
}